// round 3
// baseline (speedup 1.0000x reference)
#include <cuda_runtime.h>
#include <stdint.h>

// ---------------- problem constants ----------------
#define T_    4
#define B_    2
#define NW    64     // windows (wt*wh*ww = 4*4*4)
#define WS    128    // tokens per window (pt*ph*pw = 2*8*8)
#define C_    256
#define H_    8
#define HD    32
#define TOPK  4
#define NGRP  (T_*B_*NW)     // 512 (t,b,n) groups
#define MROWS (NGRP*WS)      // 65536 rows

// ---------------- device scratch (no allocs allowed) ----------------
__device__ float    g_region[B_*NW*C_];          // [B,nw,C]
__device__ int      g_idx[B_*NW*TOPK];           // routed window indices
__device__ unsigned g_qb[NGRP*H_*WS];            // packed spikes: bit d = channel h*32+d
__device__ unsigned g_kb[NGRP*H_*WS];
__device__ unsigned g_vb[NGRP*H_*WS];
__device__ float    g_attn[(size_t)MROWS*C_];    // attention output, 64MB

// row (grp = (t*B+b)*NW+n, s) -> offset (in floats) of x[t,b,lt,lh,lw,0]
__device__ __forceinline__ int x_row_off(int grp, int s) {
    int n  = grp & 63;
    int tb = grp >> 6;                    // t*B+b
    int iwt = n >> 4, iwh = (n >> 2) & 3, iww = n & 3;
    int ipt = s >> 6, iph = (s >> 3) & 7, ipw = s & 7;
    int lt = iwt*2 + ipt;                 // pt = 2
    int lh = iwh*8 + iph;                 // ph = 8
    int lw = iww*8 + ipw;                 // pw = 8
    return (((tb*8 + lt)*32 + lh)*32 + lw) * C_;
}

// ---------------- K1: region = xw.sum(T).mean(ws)  -> [B,nw,C] ----------------
__global__ void region_kernel(const float* __restrict__ x) {
    int bn = blockIdx.x;           // b*64 + n
    int b  = bn >> 6, n = bn & 63;
    int c  = threadIdx.x;          // 256 threads
    float acc = 0.f;
    for (int t = 0; t < T_; t++) {
        int grp = (t*B_ + b)*NW + n;
        #pragma unroll 4
        for (int s = 0; s < WS; s++) {
            acc += x[x_row_off(grp, s) + c];
        }
    }
    g_region[bn*C_ + c] = acc * (1.0f / WS);
}

// ---------------- K2: routing scores + top-4 per (b,i) ----------------
__global__ void route_kernel() {
    int bi = blockIdx.x;           // b*64 + i
    int b  = bi >> 6;
    __shared__ float sI[C_];
    __shared__ float sc[NW];
    for (int c = threadIdx.x; c < C_; c += blockDim.x)
        sI[c] = g_region[bi*C_ + c];
    __syncthreads();
    int j = threadIdx.x;           // 64 threads
    if (j < NW) {
        const float* rj = &g_region[(b*NW + j)*C_];
        float d = 0.f;
        #pragma unroll 8
        for (int c = 0; c < C_; c++) d += sI[c] * rj[c];
        sc[j] = d;                 // positive scale omitted: ordering unchanged
    }
    __syncthreads();
    if (threadIdx.x == 0) {
        unsigned long long taken = 0ull;
        for (int r = 0; r < TOPK; r++) {
            float best = -1e30f; int bj = 0;
            for (int jj = 0; jj < NW; jj++) {
                if (!((taken >> jj) & 1ull) && sc[jj] > best) { best = sc[jj]; bj = jj; }
            }
            taken |= 1ull << bj;
            g_idx[bi*TOPK + r] = bj;
        }
    }
}

// ---------------- K3: QKV GEMM (fp32) + LIF threshold + bitpack ----------------
// [65536 x 256] @ [256 x 768], BM=BN=64, BK=16, 256 threads, 4x4 microtile.
__global__ void qkv_gemm_kernel(const float* __restrict__ x,
                                const float* __restrict__ Wqkv,
                                const float* __restrict__ bqkv) {
    __shared__ __align__(16) float As[16][68];   // [kk][row], padded
    __shared__ __align__(16) float Bs[16][64];   // [kk][col]
    __shared__ __align__(16) float Cs[64][68];   // results, padded
    __shared__ int s_off[64];

    int tid = threadIdx.x;
    int bx = blockIdx.x, by = blockIdx.y;
    int row0 = by * 64;
    if (tid < 64) {
        int r = row0 + tid;
        s_off[tid] = x_row_off(r >> 7, r & 127);
    }
    int tx = tid & 15, ty = tid >> 4;
    int arow = tid >> 2, akk = (tid & 3) * 4;    // A load: row, k-quad
    int bkk  = tid >> 4, bnn = (tid & 15) * 4;   // B load: k, col-quad
    float bias[4];
    #pragma unroll
    for (int jj = 0; jj < 4; jj++) bias[jj] = bqkv[bx*64 + tx*4 + jj];
    __syncthreads();

    float c[4][4] = {};
    for (int k0 = 0; k0 < C_; k0 += 16) {
        float4 av = *(const float4*)&x[s_off[arow] + k0 + akk];
        float4 bv = *(const float4*)&Wqkv[(k0 + bkk)*(3*C_) + bx*64 + bnn];
        __syncthreads();
        As[akk+0][arow] = av.x; As[akk+1][arow] = av.y;
        As[akk+2][arow] = av.z; As[akk+3][arow] = av.w;
        *(float4*)&Bs[bkk][bnn] = bv;
        __syncthreads();
        #pragma unroll
        for (int kk = 0; kk < 16; kk++) {
            float4 a4 = *(const float4*)&As[kk][ty*4];
            float4 b4 = *(const float4*)&Bs[kk][tx*4];
            float av_[4] = {a4.x, a4.y, a4.z, a4.w};
            float bv_[4] = {b4.x, b4.y, b4.z, b4.w};
            #pragma unroll
            for (int i = 0; i < 4; i++)
                #pragma unroll
                for (int jj = 0; jj < 4; jj++)
                    c[i][jj] += av_[i] * bv_[jj];
        }
    }
    #pragma unroll
    for (int i = 0; i < 4; i++) {
        float4 o = make_float4(c[i][0]+bias[0], c[i][1]+bias[1],
                               c[i][2]+bias[2], c[i][3]+bias[3]);
        *(float4*)&Cs[ty*4 + i][tx*4] = o;
    }
    __syncthreads();

    // pack: 64 rows x 2 words (32 cols each). lif(x) = (x >= 2.0f)
    if (tid < 128) {
        int lr = tid >> 1, wloc = tid & 1;
        unsigned w = 0;
        #pragma unroll
        for (int d = 0; d < 32; d++)
            if (Cs[lr][wloc*32 + d] >= 2.0f) w |= 1u << d;
        int r = row0 + lr, grp = r >> 7, s = r & 127;
        int wcol = bx*2 + wloc;              // global word col 0..23
        int arr = wcol >> 3, hh = wcol & 7;
        unsigned* dst = (arr == 0) ? g_qb : ((arr == 1) ? g_kb : g_vb);
        dst[(grp*H_ + hh)*WS + s] = w;
    }
}

// ---------------- K4: bit-exact linear attention via popcount ----------------
// one block per (t,b,n) group; one warp per head.
__global__ void attn_kernel() {
    int grp = blockIdx.x;                     // 0..511
    int n = grp & 63, tb = grp >> 6, b = tb % B_;
    int wid = threadIdx.x >> 5, lane = threadIdx.x & 31;
    __shared__ int s_idx[TOPK];
    __shared__ int s_ks[H_][32];
    if (threadIdx.x < TOPK)
        s_idx[threadIdx.x] = g_idx[(b*NW + n)*TOPK + threadIdx.x];
    __syncthreads();

    int h = wid;
    unsigned kv[32];
    #pragma unroll
    for (int d = 0; d < 32; d++) kv[d] = 0;
    unsigned ksum = 0;                        // lane d accumulates ksum_d

    for (int j = 0; j < TOPK; j++) {
        int gsrc = tb*NW + s_idx[j];
        const unsigned* kp = &g_kb[(gsrc*H_ + h)*WS];
        const unsigned* vp = &g_vb[(gsrc*H_ + h)*WS];
        #pragma unroll
        for (int cc = 0; cc < WS/32; cc++) {
            unsigned kw = kp[cc*32 + lane];
            unsigned vw = vp[cc*32 + lane];
            unsigned kmask = 0, vmask = 0;    // lane d: 32-token bitset of channel-bit d
            #pragma unroll
            for (int e = 0; e < 32; e++) {
                unsigned mk = __ballot_sync(0xffffffffu, (kw >> e) & 1u);
                unsigned mv = __ballot_sync(0xffffffffu, (vw >> e) & 1u);
                if (lane == e) { kmask = mk; vmask = mv; }
            }
            ksum += __popc(kmask);
            #pragma unroll
            for (int d = 0; d < 32; d++) {
                unsigned km = __shfl_sync(0xffffffffu, kmask, d);
                kv[d] += __popc(km & vmask);  // kv[d][e=lane]
            }
        }
    }
    s_ks[h][lane] = (int)ksum;
    __syncwarp();

    const unsigned* qp = &g_qb[(grp*H_ + h)*WS];
    float* outp = &g_attn[(size_t)(grp*WS)*C_ + h*HD];
    for (int cc = 0; cc < 4; cc++) {
        unsigned qwl = qp[cc*32 + lane];
        #pragma unroll
        for (int i = 0; i < 32; i++) {
            unsigned qw = __shfl_sync(0xffffffffu, qwl, i);
            int acc = 0, Dv = 0;
            #pragma unroll
            for (int d = 0; d < 32; d++) {
                if ((qw >> d) & 1u) { acc += (int)kv[d]; Dv += s_ks[h][d]; }
            }
            int s = cc*32 + i;
            outp[(size_t)s*C_ + lane] = (float)acc / ((float)Dv + 1e-6f);
        }
    }
}

// ---------------- K5: proj GEMM + bias + un-windowize scatter ----------------
__global__ void proj_gemm_kernel(const float* __restrict__ Wproj,
                                 const float* __restrict__ bproj,
                                 float* __restrict__ dout) {
    __shared__ __align__(16) float As[16][68];
    __shared__ __align__(16) float Bs[16][64];
    __shared__ int s_off[64];

    int tid = threadIdx.x;
    int bx = blockIdx.x, by = blockIdx.y;
    int row0 = by * 64;
    if (tid < 64) {
        int r = row0 + tid;
        s_off[tid] = x_row_off(r >> 7, r & 127);
    }
    int tx = tid & 15, ty = tid >> 4;
    int arow = tid >> 2, akk = (tid & 3) * 4;
    int bkk  = tid >> 4, bnn = (tid & 15) * 4;
    float bias[4];
    #pragma unroll
    for (int jj = 0; jj < 4; jj++) bias[jj] = bproj[bx*64 + tx*4 + jj];
    __syncthreads();

    float c[4][4] = {};
    for (int k0 = 0; k0 < C_; k0 += 16) {
        float4 av = *(const float4*)&g_attn[(size_t)(row0 + arow)*C_ + k0 + akk];
        float4 bv = *(const float4*)&Wproj[(k0 + bkk)*C_ + bx*64 + bnn];
        __syncthreads();
        As[akk+0][arow] = av.x; As[akk+1][arow] = av.y;
        As[akk+2][arow] = av.z; As[akk+3][arow] = av.w;
        *(float4*)&Bs[bkk][bnn] = bv;
        __syncthreads();
        #pragma unroll
        for (int kk = 0; kk < 16; kk++) {
            float4 a4 = *(const float4*)&As[kk][ty*4];
            float4 b4 = *(const float4*)&Bs[kk][tx*4];
            float av_[4] = {a4.x, a4.y, a4.z, a4.w};
            float bv_[4] = {b4.x, b4.y, b4.z, b4.w};
            #pragma unroll
            for (int i = 0; i < 4; i++)
                #pragma unroll
                for (int jj = 0; jj < 4; jj++)
                    c[i][jj] += av_[i] * bv_[jj];
        }
    }
    #pragma unroll
    for (int i = 0; i < 4; i++) {
        int lr = ty*4 + i;
        float4 o = make_float4(c[i][0]+bias[0], c[i][1]+bias[1],
                               c[i][2]+bias[2], c[i][3]+bias[3]);
        *(float4*)&dout[s_off[lr] + bx*64 + tx*4] = o;
    }
}

// ---------------- launcher ----------------
extern "C" void kernel_launch(void* const* d_in, const int* in_sizes, int n_in,
                              void* d_out, int out_size) {
    const float* x      = (const float*)d_in[0];
    const float* W_qkv  = (const float*)d_in[1];
    const float* b_qkv  = (const float*)d_in[2];
    const float* W_proj = (const float*)d_in[3];
    const float* b_proj = (const float*)d_in[4];
    float* out = (float*)d_out;

    region_kernel<<<B_*NW, 256>>>(x);
    route_kernel<<<B_*NW, 64>>>();
    qkv_gemm_kernel<<<dim3(3*C_/64, MROWS/64), 256>>>(x, W_qkv, b_qkv);
    attn_kernel<<<NGRP, H_*32>>>();
    proj_gemm_kernel<<<dim3(C_/64, MROWS/64), 256>>>(W_proj, b_proj, out);
}

// round 7
// speedup vs baseline: 1.5580x; 1.5580x over previous
#include <cuda_runtime.h>
#include <cuda_bf16.h>
#include <stdint.h>

// ---------------- problem constants ----------------
#define T_    4
#define B_    2
#define NW    64
#define WS    128
#define C_    256
#define H_    8
#define TOPK  4
#define NGRP  512        // T*B*NW
#define MROWS 65536      // NGRP*WS
#define MARGIN 2e-3f

// ---------------- device scratch ----------------
__device__ float    g_region[B_*NW*C_];
__device__ int      g_idx[B_*NW*TOPK];
__device__ unsigned g_qb[NGRP*H_*WS];
__device__ unsigned g_kb[NGRP*H_*WS];
__device__ unsigned g_vb[NGRP*H_*WS];
__device__ unsigned g_kt[NGRP*H_*4*32];     // transposed K bitsets [gh][cc][d]
__device__ unsigned g_vt[NGRP*H_*4*32];
__device__ __nv_bfloat16 g_xh[(size_t)MROWS*C_];   // gathered x, hi/lo split
__device__ __nv_bfloat16 g_xl[(size_t)MROWS*C_];
__device__ __nv_bfloat16 g_ah[(size_t)MROWS*C_];   // attention out, hi/lo split
__device__ __nv_bfloat16 g_al[(size_t)MROWS*C_];
__device__ __nv_bfloat16 g_Wq_hi[768*256], g_Wq_lo[768*256];   // [n][k]
__device__ __nv_bfloat16 g_Wp_hi[256*256], g_Wp_lo[256*256];

// row (grp, s) -> float offset of x[t,b,lt,lh,lw,0]
__device__ __forceinline__ int x_row_off(int grp, int s) {
    int n  = grp & 63;
    int tb = grp >> 6;
    int iwt = n >> 4, iwh = (n >> 2) & 3, iww = n & 3;
    int ipt = s >> 6, iph = (s >> 3) & 7, ipw = s & 7;
    int lt = iwt*2 + ipt;
    int lh = iwh*8 + iph;
    int lw = iww*8 + ipw;
    return (((tb*8 + lt)*32 + lh)*32 + lw) * C_;
}

__device__ __forceinline__ uint32_t smem_to_u32(const void* p) {
    uint32_t a;
    asm("{ .reg .u64 t; cvta.to.shared.u64 t, %1; cvt.u32.u64 %0, t; }" : "=r"(a) : "l"(p));
    return a;
}
__device__ __forceinline__ void cp16(uint32_t dst, const void* src) {
    asm volatile("cp.async.cg.shared.global [%0], [%1], 16;" :: "r"(dst), "l"(src));
}
__device__ __forceinline__ void mma16816(float* c, const uint32_t* a, const uint32_t* b) {
    asm volatile(
        "mma.sync.aligned.m16n8k16.row.col.f32.bf16.bf16.f32 "
        "{%0,%1,%2,%3}, {%4,%5,%6,%7}, {%8,%9}, {%0,%1,%2,%3};"
        : "+f"(c[0]), "+f"(c[1]), "+f"(c[2]), "+f"(c[3])
        : "r"(a[0]), "r"(a[1]), "r"(a[2]), "r"(a[3]), "r"(b[0]), "r"(b[1]));
}

// fp32 sequential-fma recompute (same accumulation structure that matched the
// reference bit-for-bit on spikes in round 3). Used only near the threshold.
__device__ float refine_dot(const float* __restrict__ x, const float* __restrict__ W,
                            int by, int s, int col) {
    const float* xr = x + x_row_off(by, s);
    const float* wc = W + col;                 // W[k][col], row stride 768
    float acc = 0.f;
    for (int k = 0; k < 256; k++)
        acc = fmaf(xr[k], wc[(size_t)k * 768], acc);
    return acc;
}

// ---------------- K0a: windowize gather + hi/lo split of x ----------------
__global__ void gather_split_kernel(const float* __restrict__ x) {
    int row = blockIdx.x;
    int c = threadIdx.x;
    float v = x[x_row_off(row >> 7, row & 127) + c];
    __nv_bfloat16 hi = __float2bfloat16_rn(v);
    __nv_bfloat16 lo = __float2bfloat16_rn(v - __bfloat162float(hi));
    g_xh[(size_t)row*C_ + c] = hi;
    g_xl[(size_t)row*C_ + c] = lo;
}

// ---------------- K0b: W transpose + hi/lo split ----------------
__global__ void wtrans_kernel(const float* __restrict__ Wqkv,
                              const float* __restrict__ Wproj) {
    int idx = blockIdx.x*256 + threadIdx.x;
    if (idx < 256*768) {
        int k = idx / 768, n = idx % 768;
        float v = Wqkv[idx];
        __nv_bfloat16 hi = __float2bfloat16_rn(v);
        __nv_bfloat16 lo = __float2bfloat16_rn(v - __bfloat162float(hi));
        g_Wq_hi[n*256 + k] = hi;
        g_Wq_lo[n*256 + k] = lo;
    }
    if (idx < 256*256) {
        int k = idx / 256, n = idx % 256;
        float v = Wproj[idx];
        __nv_bfloat16 hi = __float2bfloat16_rn(v);
        __nv_bfloat16 lo = __float2bfloat16_rn(v - __bfloat162float(hi));
        g_Wp_hi[n*256 + k] = hi;
        g_Wp_lo[n*256 + k] = lo;
    }
}

// ---------------- K1: region ----------------
__global__ void region_kernel(const float* __restrict__ x) {
    int bn = blockIdx.x;
    int b  = bn >> 6, n = bn & 63;
    int c  = threadIdx.x;
    float acc = 0.f;
    for (int t = 0; t < T_; t++) {
        int grp = (t*B_ + b)*NW + n;
        #pragma unroll 4
        for (int s = 0; s < WS; s++) acc += x[x_row_off(grp, s) + c];
    }
    g_region[bn*C_ + c] = acc * (1.0f / WS);
}

// ---------------- K2: routing top-4 ----------------
__global__ void route_kernel() {
    int bi = blockIdx.x;
    int b  = bi >> 6;
    __shared__ float sI[C_];
    __shared__ float sc[NW];
    for (int c = threadIdx.x; c < C_; c += blockDim.x)
        sI[c] = g_region[bi*C_ + c];
    __syncthreads();
    int j = threadIdx.x;
    if (j < NW) {
        const float* rj = &g_region[(b*NW + j)*C_];
        float d = 0.f;
        #pragma unroll 8
        for (int c = 0; c < C_; c++) d += sI[c] * rj[c];
        sc[j] = d;
    }
    __syncthreads();
    if (threadIdx.x == 0) {
        unsigned long long taken = 0ull;
        for (int r = 0; r < TOPK; r++) {
            float best = -1e30f; int bj = 0;
            for (int jj = 0; jj < NW; jj++)
                if (!((taken >> jj) & 1ull) && sc[jj] > best) { best = sc[jj]; bj = jj; }
            taken |= 1ull << bj;
            g_idx[bi*TOPK + r] = bj;
        }
    }
}

// ---------------- K3/K6: split-bf16 GEMM via mma.sync ----------------
// MODE 0: A = g_x (gathered), B = Wqkv (N=768), epi = bias+LIF(+refine)+bitpack
// MODE 1: A = g_a (attn out), B = Wproj (N=256), epi = bias+un-windowize
// Tile 128x128, K-chunk 16, double-buffered cp.async, 8 warps (2x4), 48KB smem.
#define RSTRIDE 48                 // bytes per smem row (16 bf16 + 8 pad)
#define MATB    (128*RSTRIDE)      // 6144
#define STAGEB  (4*MATB)           // 24576: [Ahi][Alo][Bhi][Blo]

template<int MODE>
__global__ void __launch_bounds__(256)
gemm_mma_kernel(const float* __restrict__ bias_g, float* __restrict__ out,
                const float* __restrict__ x_full, const float* __restrict__ W_full) {
    __shared__ __align__(16) char smem[2*STAGEB];   // 49152 = 48KB
    uint32_t sb = smem_to_u32(smem);
    int tid = threadIdx.x, lane = tid & 31, wid = tid >> 5;
    int warp_m = wid & 1, warp_n = wid >> 1;         // 2 x 4
    int bx = blockIdx.x, by = blockIdx.y;

    const __nv_bfloat16* Ah = (MODE == 0) ? g_xh : g_ah;
    const __nv_bfloat16* Al = (MODE == 0) ? g_xl : g_al;
    const __nv_bfloat16* Bh = (MODE == 0) ? g_Wq_hi : g_Wp_hi;
    const __nv_bfloat16* Bl = (MODE == 0) ? g_Wq_lo : g_Wp_lo;
    size_t arow0 = (size_t)by * 128 * 256;
    size_t brow0 = (size_t)bx * 128 * 256;

    float bv[4][2];
    #pragma unroll
    for (int ni = 0; ni < 4; ni++) {
        int col = bx*128 + warp_n*32 + ni*8 + 2*(lane & 3);
        bv[ni][0] = bias_g[col];
        bv[ni][1] = bias_g[col + 1];
    }

    auto stage_load = [&](int c, int s) {
        uint32_t base = sb + s*STAGEB;
        int vec = tid;
        int row = vec >> 1, half = vec & 1;
        uint32_t doff = row*RSTRIDE + half*16;
        size_t gsrc = (size_t)row*256 + c*16 + half*8;
        cp16(base + 0*MATB + doff, Ah + arow0 + gsrc);
        cp16(base + 1*MATB + doff, Al + arow0 + gsrc);
        cp16(base + 2*MATB + doff, Bh + brow0 + gsrc);
        cp16(base + 3*MATB + doff, Bl + brow0 + gsrc);
        asm volatile("cp.async.commit_group;" ::: "memory");
    };

    float c[4][4][4];
    #pragma unroll
    for (int i = 0; i < 4; i++)
        #pragma unroll
        for (int j = 0; j < 4; j++)
            #pragma unroll
            for (int k = 0; k < 4; k++) c[i][j][k] = 0.f;

    stage_load(0, 0);
    for (int ch = 0; ch < 16; ch++) {
        if (ch < 15) {
            stage_load(ch + 1, (ch + 1) & 1);
            asm volatile("cp.async.wait_group 1;" ::: "memory");
        } else {
            asm volatile("cp.async.wait_group 0;" ::: "memory");
        }
        __syncthreads();
        uint32_t stb = sb + (ch & 1)*STAGEB;

        uint32_t bh[4][2], bl[4][2];
        #pragma unroll
        for (int ni = 0; ni < 4; ni++) {
            int n = warp_n*32 + ni*8 + (lane & 7);
            uint32_t off = n*RSTRIDE + ((lane >> 3) & 1)*16;
            uint32_t ab = stb + 2*MATB + off;
            asm volatile("ldmatrix.sync.aligned.m8n8.x2.shared.b16 {%0,%1}, [%2];"
                : "=r"(bh[ni][0]), "=r"(bh[ni][1]) : "r"(ab));
            asm volatile("ldmatrix.sync.aligned.m8n8.x2.shared.b16 {%0,%1}, [%2];"
                : "=r"(bl[ni][0]), "=r"(bl[ni][1]) : "r"(ab + MATB));
        }
        #pragma unroll
        for (int mi = 0; mi < 4; mi++) {
            int m = warp_m*64 + mi*16 + (lane & 15);
            uint32_t off = m*RSTRIDE + (lane >> 4)*16;
            uint32_t aa = stb + off;
            uint32_t ah_[4], al_[4];
            asm volatile("ldmatrix.sync.aligned.m8n8.x4.shared.b16 {%0,%1,%2,%3}, [%4];"
                : "=r"(ah_[0]), "=r"(ah_[1]), "=r"(ah_[2]), "=r"(ah_[3]) : "r"(aa));
            asm volatile("ldmatrix.sync.aligned.m8n8.x4.shared.b16 {%0,%1,%2,%3}, [%4];"
                : "=r"(al_[0]), "=r"(al_[1]), "=r"(al_[2]), "=r"(al_[3]) : "r"(aa + MATB));
            #pragma unroll
            for (int ni = 0; ni < 4; ni++) {
                mma16816(c[mi][ni], ah_, bh[ni]);
                mma16816(c[mi][ni], ah_, bl[ni]);
                mma16816(c[mi][ni], al_, bh[ni]);
            }
        }
        __syncthreads();
    }

    // ---------------- epilogue ----------------
    if (MODE == 0) {
        #pragma unroll
        for (int mi = 0; mi < 4; mi++) {
            #pragma unroll
            for (int half = 0; half < 2; half++) {
                int s = warp_m*64 + mi*16 + half*8 + (lane >> 2);
                unsigned w = 0;
                #pragma unroll
                for (int ni = 0; ni < 4; ni++) {
                    int col = bx*128 + warp_n*32 + ni*8 + 2*(lane & 3);
                    float v0 = c[mi][ni][half*2 + 0] + bv[ni][0];
                    float v1 = c[mi][ni][half*2 + 1] + bv[ni][1];
                    // near-threshold: recompute in reference-matching fp32 order
                    if (fabsf(v0 - 2.0f) < MARGIN)
                        v0 = refine_dot(x_full, W_full, by, s, col) + bv[ni][0];
                    if (fabsf(v1 - 2.0f) < MARGIN)
                        v1 = refine_dot(x_full, W_full, by, s, col + 1) + bv[ni][1];
                    int sh = ni*8 + 2*(lane & 3);
                    w |= (v0 >= 2.0f ? 1u : 0u) << sh;
                    w |= (v1 >= 2.0f ? 1u : 0u) << (sh + 1);
                }
                w |= __shfl_xor_sync(0xffffffffu, w, 1);
                w |= __shfl_xor_sync(0xffffffffu, w, 2);
                if ((lane & 3) == 0) {
                    int wcol = bx*4 + warp_n;          // 0..23
                    unsigned* dst = (wcol < 8) ? g_qb : ((wcol < 16) ? g_kb : g_vb);
                    dst[(by*H_ + (wcol & 7))*WS + s] = w;
                }
            }
        }
    } else {
        #pragma unroll
        for (int mi = 0; mi < 4; mi++) {
            #pragma unroll
            for (int half = 0; half < 2; half++) {
                int s = warp_m*64 + mi*16 + half*8 + (lane >> 2);
                int xo = x_row_off(by, s) + bx*128 + warp_n*32;
                #pragma unroll
                for (int ni = 0; ni < 4; ni++) {
                    float2 o;
                    o.x = c[mi][ni][half*2 + 0] + bv[ni][0];
                    o.y = c[mi][ni][half*2 + 1] + bv[ni][1];
                    *(float2*)&out[xo + ni*8 + 2*(lane & 3)] = o;
                }
            }
        }
    }
}

// ---------------- K4: per-window bit transpose ----------------
__global__ void transpose_kernel() {
    int grp = blockIdx.x;
    int wid = threadIdx.x >> 5, lane = threadIdx.x & 31;
    int h = wid;
    int base = (grp*H_ + h);
    #pragma unroll
    for (int cc = 0; cc < 4; cc++) {
        unsigned kw = g_kb[base*WS + cc*32 + lane];
        unsigned vw = g_vb[base*WS + cc*32 + lane];
        unsigned kt = 0, vt = 0;
        #pragma unroll
        for (int d = 0; d < 32; d++) {
            unsigned mk = __ballot_sync(0xffffffffu, (kw >> d) & 1u);
            unsigned mv = __ballot_sync(0xffffffffu, (vw >> d) & 1u);
            if (lane == d) { kt = mk; vt = mv; }
        }
        g_kt[(base*4 + cc)*32 + lane] = kt;
        g_vt[(base*4 + cc)*32 + lane] = vt;
    }
}

// ---------------- K5: popcount linear attention -> split bf16 out ----------------
__global__ void attn_kernel() {
    int grp = blockIdx.x;
    int n = grp & 63, tb = grp >> 6, b = tb % B_;
    int wid = threadIdx.x >> 5, lane = threadIdx.x & 31;
    __shared__ int s_idx[TOPK];
    __shared__ int s_ks[H_][32];
    if (threadIdx.x < TOPK)
        s_idx[threadIdx.x] = g_idx[(b*NW + n)*TOPK + threadIdx.x];
    __syncthreads();

    int h = wid;
    unsigned kv[32];
    #pragma unroll
    for (int d = 0; d < 32; d++) kv[d] = 0;
    unsigned ksum = 0;

    for (int j = 0; j < TOPK; j++) {
        int gsrc = tb*NW + s_idx[j];
        const unsigned* ktp = &g_kt[(gsrc*H_ + h)*4*32];
        const unsigned* vtp = &g_vt[(gsrc*H_ + h)*4*32];
        #pragma unroll
        for (int cc = 0; cc < 4; cc++) {
            unsigned ktw = ktp[cc*32 + lane];
            unsigned vtw = vtp[cc*32 + lane];
            ksum += __popc(ktw);
            #pragma unroll
            for (int d = 0; d < 32; d++) {
                unsigned km = __shfl_sync(0xffffffffu, ktw, d);
                kv[d] += __popc(km & vtw);
            }
        }
    }
    s_ks[h][lane] = (int)ksum;
    __syncwarp();

    const unsigned* qp = &g_qb[(grp*H_ + h)*WS];
    for (int cc = 0; cc < 4; cc++) {
        unsigned qwl = qp[cc*32 + lane];
        #pragma unroll
        for (int i = 0; i < 32; i++) {
            unsigned qw = __shfl_sync(0xffffffffu, qwl, i);
            int acc = 0, Dv = 0;
            #pragma unroll
            for (int d = 0; d < 32; d++) {
                if ((qw >> d) & 1u) { acc += (int)kv[d]; Dv += s_ks[h][d]; }
            }
            int s = cc*32 + i;
            float o = (float)acc / ((float)Dv + 1e-6f);
            __nv_bfloat16 hi = __float2bfloat16_rn(o);
            __nv_bfloat16 lo = __float2bfloat16_rn(o - __bfloat162float(hi));
            size_t off = ((size_t)(grp*WS + s))*C_ + h*32 + lane;
            g_ah[off] = hi;
            g_al[off] = lo;
        }
    }
}

// ---------------- launcher ----------------
extern "C" void kernel_launch(void* const* d_in, const int* in_sizes, int n_in,
                              void* d_out, int out_size) {
    const float* x      = (const float*)d_in[0];
    const float* W_qkv  = (const float*)d_in[1];
    const float* b_qkv  = (const float*)d_in[2];
    const float* W_proj = (const float*)d_in[3];
    const float* b_proj = (const float*)d_in[4];
    float* out = (float*)d_out;

    gather_split_kernel<<<MROWS, 256>>>(x);
    wtrans_kernel<<<768, 256>>>(W_qkv, W_proj);
    region_kernel<<<B_*NW, 256>>>(x);
    route_kernel<<<B_*NW, 64>>>();
    gemm_mma_kernel<0><<<dim3(6, NGRP), 256>>>(b_qkv, nullptr, x, W_qkv);
    transpose_kernel<<<NGRP, 256>>>();
    attn_kernel<<<NGRP, 256>>>();
    gemm_mma_kernel<1><<<dim3(2, NGRP), 256>>>(b_proj, out, nullptr, nullptr);
}